// round 1
// baseline (speedup 1.0000x reference)
#include <cuda_runtime.h>

#define NN  100000
#define NE  1600000
#define CH  128
#define LAT 64

// ---------------- scratch (no allocations allowed) ----------------
__device__ float d_A[(size_t)NN * CH];   // h0 = x @ W1
__device__ float d_B[(size_t)NN * CH];   // scatter accumulator (reused)
__device__ float d_Cb[(size_t)NN * CH];  // h = relu(conv1)
__device__ float d_dis[NN];              // deg -> deg^-1/2
__device__ int   d_is64;                 // edge_index element width flag

// ---------------- edge index width detection ----------------
// int64 values < 2^31 -> every odd 32-bit word is 0. As int32 data, odd words
// are random values in [0,100000): P(all zero over 4096 samples) ~ 0.
__global__ void k_detect(const int* __restrict__ ei32) {
    __shared__ int any;
    if (threadIdx.x == 0) any = 0;
    __syncthreads();
    for (int i = threadIdx.x; i < 4096; i += blockDim.x)
        if (ei32[2 * i + 1] != 0) any = 1;
    __syncthreads();
    if (threadIdx.x == 0) d_is64 = (any == 0) ? 1 : 0;
}

__device__ __forceinline__ int edge_idx(const void* ei, int part, int e) {
    if (d_is64) return (int)((const long long*)ei)[(size_t)part * NE + e];
    return ((const int*)ei)[(size_t)part * NE + e];
}

// ---------------- degree / normalization ----------------
__global__ void k_init_deg() {
    int i = blockIdx.x * 256 + threadIdx.x;
    if (i < NN) d_dis[i] = 1.0f;                 // self loop contributes 1
}
__global__ void k_edge_deg(const void* __restrict__ ei) {
    int i = blockIdx.x * 256 + threadIdx.x;
    if (i < NE) atomicAdd(&d_dis[edge_idx(ei, 1, i)], 1.0f);
}
__global__ void k_dis() {
    int i = blockIdx.x * 256 + threadIdx.x;
    if (i < NN) d_dis[i] = rsqrtf(d_dis[i]);     // deg >= 1 always
}
__global__ void k_zeroB() {
    int i = blockIdx.x * 256 + threadIdx.x;
    if (i < NN * (CH / 4)) ((float4*)d_B)[i] = make_float4(0.f, 0.f, 0.f, 0.f);
}

// ---------------- GEMM1: d_A = x @ W1   (100000x128 @ 128x128) ----------------
__global__ __launch_bounds__(256) void k_gemm1(const float* __restrict__ x,
                                               const float* __restrict__ W) {
    __shared__ float sX[32][36];        // padded to dodge bank conflicts
    __shared__ float sW[32][CH];
    int tid  = threadIdx.x;
    int row0 = blockIdx.x * 32;
    int rg = tid >> 4, cg = tid & 15;   // compute map: 2 rows x (4+4) cols
    int lr = tid >> 3, lc = (tid & 7) * 4;  // load map

    float a0c[8] = {0,0,0,0,0,0,0,0};
    float a1c[8] = {0,0,0,0,0,0,0,0};

    for (int kc = 0; kc < CH; kc += 32) {
        float4 xv = *(const float4*)(x + (size_t)(row0 + lr) * CH + kc + lc);
        *(float4*)&sX[lr][lc] = xv;
        const float4* W4 = (const float4*)(W + (size_t)kc * CH);
        float4* sW4 = (float4*)sW;
#pragma unroll
        for (int i = 0; i < 4; i++) sW4[tid + i * 256] = W4[tid + i * 256];
        __syncthreads();
#pragma unroll
        for (int k = 0; k < 32; k++) {
            float a0 = sX[rg * 2][k];
            float a1 = sX[rg * 2 + 1][k];
            float4 w0 = *(const float4*)&sW[k][cg * 4];
            float4 w1 = *(const float4*)&sW[k][64 + cg * 4];
            a0c[0] += a0 * w0.x; a0c[1] += a0 * w0.y; a0c[2] += a0 * w0.z; a0c[3] += a0 * w0.w;
            a0c[4] += a0 * w1.x; a0c[5] += a0 * w1.y; a0c[6] += a0 * w1.z; a0c[7] += a0 * w1.w;
            a1c[0] += a1 * w0.x; a1c[1] += a1 * w0.y; a1c[2] += a1 * w0.z; a1c[3] += a1 * w0.w;
            a1c[4] += a1 * w1.x; a1c[5] += a1 * w1.y; a1c[6] += a1 * w1.z; a1c[7] += a1 * w1.w;
        }
        __syncthreads();
    }
    size_t r = (size_t)(row0 + rg * 2);
    *(float4*)&d_A[r * CH + cg * 4]            = make_float4(a0c[0], a0c[1], a0c[2], a0c[3]);
    *(float4*)&d_A[r * CH + 64 + cg * 4]       = make_float4(a0c[4], a0c[5], a0c[6], a0c[7]);
    *(float4*)&d_A[(r + 1) * CH + cg * 4]      = make_float4(a1c[0], a1c[1], a1c[2], a1c[3]);
    *(float4*)&d_A[(r + 1) * CH + 64 + cg * 4] = make_float4(a1c[4], a1c[5], a1c[6], a1c[7]);
}

// ---------------- edge scatter: d_B[col] += norm * src[row] ----------------
// One warp per edge, float4 per lane, vector reduction to L2 (sm_90+).
__global__ __launch_bounds__(256) void k_scatter(const void* __restrict__ ei, int which) {
    int e = (blockIdx.x * 256 + threadIdx.x) >> 5;
    if (e >= NE) return;
    int lane = threadIdx.x & 31;
    const float* __restrict__ src = which ? d_Cb : d_A;
    int r = edge_idx(ei, 0, e);
    int c = edge_idx(ei, 1, e);
    float nrm = d_dis[r] * d_dis[c];
    float4 v = *(const float4*)(src + (size_t)r * CH + lane * 4);
    v.x *= nrm; v.y *= nrm; v.z *= nrm; v.w *= nrm;
    float* dst = d_B + (size_t)c * CH + lane * 4;
    asm volatile("red.global.add.v4.f32 [%0], {%1,%2,%3,%4};"
                 :: "l"(dst), "f"(v.x), "f"(v.y), "f"(v.z), "f"(v.w) : "memory");
}

// ---------------- h = relu(scatter + dis^2 * h0 + b1) ----------------
__global__ void k_relu(const float* __restrict__ b1) {
    int i = blockIdx.x * 256 + threadIdx.x;
    if (i >= NN * (CH / 4)) return;
    int node = i >> 5;
    int cp   = i & 31;
    float ds = d_dis[node];
    float s  = ds * ds;
    float4 a = ((const float4*)d_A)[i];
    float4 b = ((const float4*)d_B)[i];
    float4 bias = ((const float4*)b1)[cp];
    float4 h;
    h.x = fmaxf(fmaf(s, a.x, b.x) + bias.x, 0.f);
    h.y = fmaxf(fmaf(s, a.y, b.y) + bias.y, 0.f);
    h.z = fmaxf(fmaf(s, a.z, b.z) + bias.z, 0.f);
    h.w = fmaxf(fmaf(s, a.w, b.w) + bias.w, 0.f);
    ((float4*)d_Cb)[i] = h;
}

// ---------------- fused epilogue: g = B + dis^2*h; mu/lv GEMMs; reparam ------
__global__ __launch_bounds__(256) void k_final(const float* __restrict__ Wmu,
                                               const float* __restrict__ bmu,
                                               const float* __restrict__ Wlv,
                                               const float* __restrict__ blv,
                                               const float* __restrict__ eps,
                                               float* __restrict__ out) {
    __shared__ float sG[32][36];
    __shared__ float sMu[32 * LAT];
    __shared__ float sLv[32 * LAT];
    int tid  = threadIdx.x;
    int row0 = blockIdx.x * 32;
    int nl = tid >> 3, colg = tid & 7;      // compute: 1 node x (4+4) cols x 2 mats
    int lr = tid >> 3, lc = (tid & 7) * 4;  // load map
    int lnode = row0 + lr;
    float lds = d_dis[lnode];
    float ls  = lds * lds;

    float mu[8] = {0,0,0,0,0,0,0,0};
    float lv[8] = {0,0,0,0,0,0,0,0};

    for (int kc = 0; kc < CH; kc += 32) {
        size_t off = (size_t)lnode * CH + kc + lc;
        float4 b = *(const float4*)(d_B + off);
        float4 c = *(const float4*)(d_Cb + off);
        float4 g = make_float4(fmaf(ls, c.x, b.x), fmaf(ls, c.y, b.y),
                               fmaf(ls, c.z, b.z), fmaf(ls, c.w, b.w));
        *(float4*)&sG[lr][lc] = g;
        const float4* Wm4 = (const float4*)(Wmu + (size_t)kc * LAT);
        const float4* Wl4 = (const float4*)(Wlv + (size_t)kc * LAT);
        ((float4*)sMu)[tid]       = Wm4[tid];
        ((float4*)sMu)[tid + 256] = Wm4[tid + 256];
        ((float4*)sLv)[tid]       = Wl4[tid];
        ((float4*)sLv)[tid + 256] = Wl4[tid + 256];
        __syncthreads();
#pragma unroll
        for (int k = 0; k < 32; k++) {
            float a = sG[nl][k];
            float4 m0 = *(const float4*)&sMu[k * LAT + colg * 4];
            float4 m1 = *(const float4*)&sMu[k * LAT + 32 + colg * 4];
            float4 l0 = *(const float4*)&sLv[k * LAT + colg * 4];
            float4 l1 = *(const float4*)&sLv[k * LAT + 32 + colg * 4];
            mu[0] += a * m0.x; mu[1] += a * m0.y; mu[2] += a * m0.z; mu[3] += a * m0.w;
            mu[4] += a * m1.x; mu[5] += a * m1.y; mu[6] += a * m1.z; mu[7] += a * m1.w;
            lv[0] += a * l0.x; lv[1] += a * l0.y; lv[2] += a * l0.z; lv[3] += a * l0.w;
            lv[4] += a * l1.x; lv[5] += a * l1.y; lv[6] += a * l1.z; lv[7] += a * l1.w;
        }
        __syncthreads();
    }

    int node = row0 + nl;
    float* out_z  = out;
    float* out_mu = out + (size_t)NN * LAT;
    float* out_lv = out + 2 * (size_t)NN * LAT;
#pragma unroll
    for (int h = 0; h < 2; h++) {
        int c0 = h * 32 + colg * 4;
        float4 bm = *(const float4*)(bmu + c0);
        float4 bl = *(const float4*)(blv + c0);
        float4 ev = *(const float4*)(eps + (size_t)node * LAT + c0);
        float m0 = mu[h*4+0] + bm.x, m1 = mu[h*4+1] + bm.y,
              m2 = mu[h*4+2] + bm.z, m3 = mu[h*4+3] + bm.w;
        float l0 = lv[h*4+0] + bl.x, l1 = lv[h*4+1] + bl.y,
              l2 = lv[h*4+2] + bl.z, l3 = lv[h*4+3] + bl.w;
        float z0 = m0 + ev.x * expf(0.5f * l0);
        float z1 = m1 + ev.y * expf(0.5f * l1);
        float z2 = m2 + ev.z * expf(0.5f * l2);
        float z3 = m3 + ev.w * expf(0.5f * l3);
        size_t o = (size_t)node * LAT + c0;
        *(float4*)(out_mu + o) = make_float4(m0, m1, m2, m3);
        *(float4*)(out_lv + o) = make_float4(l0, l1, l2, l3);
        *(float4*)(out_z  + o) = make_float4(z0, z1, z2, z3);
    }
}

// ---------------- launch ----------------
extern "C" void kernel_launch(void* const* d_in, const int* in_sizes, int n_in,
                              void* d_out, int out_size) {
    const float* x   = (const float*)d_in[0];
    const void*  ei  = d_in[1];               // int32 or int64, detected on-device
    const float* W1  = (const float*)d_in[2];
    const float* b1  = (const float*)d_in[3];
    const float* Wmu = (const float*)d_in[4];
    const float* bmu = (const float*)d_in[5];
    const float* Wlv = (const float*)d_in[6];
    const float* blv = (const float*)d_in[7];
    const float* eps = (const float*)d_in[8];
    float* out = (float*)d_out;

    k_detect<<<1, 256>>>((const int*)ei);
    k_init_deg<<<(NN + 255) / 256, 256>>>();
    k_edge_deg<<<(NE + 255) / 256, 256>>>(ei);
    k_dis<<<(NN + 255) / 256, 256>>>();

    k_gemm1<<<NN / 32, 256>>>(x, W1);          // d_A = x @ W1

    k_zeroB<<<(NN * 32 + 255) / 256, 256>>>();
    k_scatter<<<NE / 8, 256>>>(ei, 0);         // d_B = A_edges * d_A
    k_relu<<<(NN * 32 + 255) / 256, 256>>>(b1); // d_Cb = relu(d_B + dis^2*d_A + b1)

    k_zeroB<<<(NN * 32 + 255) / 256, 256>>>();
    k_scatter<<<NE / 8, 256>>>(ei, 1);         // d_B = A_edges * d_Cb

    k_final<<<NN / 32, 256>>>(Wmu, bmu, Wlv, blv, eps, out);
}

// round 3
// speedup vs baseline: 1.5592x; 1.5592x over previous
#include <cuda_runtime.h>

#define NN  100000
#define NE  1600000
#define CH  128
#define LAT 64
#define NBLK_SCAN 98   // ceil(100000/1024)

// ---------------- scratch (no allocations allowed) ----------------
__device__ float d_A[(size_t)NN * CH];   // h0 = x @ W1
__device__ float d_B[(size_t)NN * CH];   // g = A * h (2nd aggregation)
__device__ float d_Cb[(size_t)NN * CH];  // h = relu(conv1)
__device__ float d_dis[NN];              // deg^-1/2
__device__ int   d_cnt[NN];              // edge-only in-degree
__device__ int   d_off[NN + 1];          // CSR offsets
__device__ int   d_pos[NN];              // fill cursors
__device__ int2  d_adj[NE];              // {src_idx, bitcast(dis[src])}
__device__ int   d_blk[128], d_blkoff[128];
__device__ int   d_is64;

// ---------------- edge index width detection ----------------
__global__ void k_detect(const int* __restrict__ ei32) {
    __shared__ int any;
    if (threadIdx.x == 0) any = 0;
    __syncthreads();
    for (int i = threadIdx.x; i < 4096; i += blockDim.x)
        if (ei32[2 * i + 1] != 0) any = 1;
    __syncthreads();
    if (threadIdx.x == 0) d_is64 = (any == 0) ? 1 : 0;
}

__device__ __forceinline__ int edge_idx(const void* ei, int part, int e) {
    if (d_is64) return (int)((const long long*)ei)[(size_t)part * NE + e];
    return ((const int*)ei)[(size_t)part * NE + e];
}

// ---------------- degree + normalization ----------------
__global__ void k_zero_cnt() {
    int i = blockIdx.x * 256 + threadIdx.x;
    if (i < NN) d_cnt[i] = 0;
}
__global__ void k_hist(const void* __restrict__ ei) {
    int i = blockIdx.x * 256 + threadIdx.x;
    if (i < NE) atomicAdd(&d_cnt[edge_idx(ei, 1, i)], 1);
}
__global__ void k_dis2() {
    int i = blockIdx.x * 256 + threadIdx.x;
    if (i < NN) d_dis[i] = rsqrtf((float)d_cnt[i] + 1.0f);  // +1 self loop
}

// ---------------- prefix sum (3 kernels) ----------------
__global__ void k_scan_local() {
    __shared__ int s[1024];
    int tid = threadIdx.x;
    int gid = blockIdx.x * 1024 + tid;
    int v = (gid < NN) ? d_cnt[gid] : 0;
    s[tid] = v;
    __syncthreads();
    for (int o = 1; o < 1024; o <<= 1) {
        int t = (tid >= o) ? s[tid - o] : 0;
        __syncthreads();
        s[tid] += t;
        __syncthreads();
    }
    if (gid < NN) d_off[gid] = s[tid] - v;       // exclusive
    if (tid == 1023) d_blk[blockIdx.x] = s[1023];
}
__global__ void k_scan_blk() {
    __shared__ int s[128];
    int tid = threadIdx.x;
    int v = (tid < NBLK_SCAN) ? d_blk[tid] : 0;
    s[tid] = v;
    __syncthreads();
    for (int o = 1; o < 128; o <<= 1) {
        int t = (tid >= o) ? s[tid - o] : 0;
        __syncthreads();
        s[tid] += t;
        __syncthreads();
    }
    d_blkoff[tid] = s[tid] - v;
}
__global__ void k_scan_add() {
    int gid = blockIdx.x * 1024 + threadIdx.x;
    if (gid < NN) {
        int o = d_off[gid] + d_blkoff[blockIdx.x];
        d_off[gid] = o;
        d_pos[gid] = o;
    }
    if (gid == 0) d_off[NN] = NE;
}

// ---------------- CSR fill: bucket edges by destination ----------------
__global__ void k_fill(const void* __restrict__ ei) {
    int e = blockIdx.x * 256 + threadIdx.x;
    if (e >= NE) return;
    int r = edge_idx(ei, 0, e);
    int c = edge_idx(ei, 1, e);
    int p = atomicAdd(&d_pos[c], 1);
    d_adj[p] = make_int2(r, __float_as_int(d_dis[r]));
}

// ---------------- GEMM1: d_A = x @ W1 ----------------
__global__ __launch_bounds__(256) void k_gemm1(const float* __restrict__ x,
                                               const float* __restrict__ W) {
    __shared__ float sX[32][36];
    __shared__ float sW[32][CH];
    int tid  = threadIdx.x;
    int row0 = blockIdx.x * 32;
    int rg = tid >> 4, cg = tid & 15;
    int lr = tid >> 3, lc = (tid & 7) * 4;

    float a0c[8] = {0,0,0,0,0,0,0,0};
    float a1c[8] = {0,0,0,0,0,0,0,0};

    for (int kc = 0; kc < CH; kc += 32) {
        float4 xv = *(const float4*)(x + (size_t)(row0 + lr) * CH + kc + lc);
        *(float4*)&sX[lr][lc] = xv;
        const float4* W4 = (const float4*)(W + (size_t)kc * CH);
        float4* sW4 = (float4*)sW;
#pragma unroll
        for (int i = 0; i < 4; i++) sW4[tid + i * 256] = W4[tid + i * 256];
        __syncthreads();
#pragma unroll
        for (int k = 0; k < 32; k++) {
            float a0 = sX[rg * 2][k];
            float a1 = sX[rg * 2 + 1][k];
            float4 w0 = *(const float4*)&sW[k][cg * 4];
            float4 w1 = *(const float4*)&sW[k][64 + cg * 4];
            a0c[0] += a0 * w0.x; a0c[1] += a0 * w0.y; a0c[2] += a0 * w0.z; a0c[3] += a0 * w0.w;
            a0c[4] += a0 * w1.x; a0c[5] += a0 * w1.y; a0c[6] += a0 * w1.z; a0c[7] += a0 * w1.w;
            a1c[0] += a1 * w0.x; a1c[1] += a1 * w0.y; a1c[2] += a1 * w0.z; a1c[3] += a1 * w0.w;
            a1c[4] += a1 * w1.x; a1c[5] += a1 * w1.y; a1c[6] += a1 * w1.z; a1c[7] += a1 * w1.w;
        }
        __syncthreads();
    }
    size_t r = (size_t)(row0 + rg * 2);
    *(float4*)&d_A[r * CH + cg * 4]            = make_float4(a0c[0], a0c[1], a0c[2], a0c[3]);
    *(float4*)&d_A[r * CH + 64 + cg * 4]       = make_float4(a0c[4], a0c[5], a0c[6], a0c[7]);
    *(float4*)&d_A[(r + 1) * CH + cg * 4]      = make_float4(a1c[0], a1c[1], a1c[2], a1c[3]);
    *(float4*)&d_A[(r + 1) * CH + 64 + cg * 4] = make_float4(a1c[4], a1c[5], a1c[6], a1c[7]);
}

// ---------------- CSR gather: one warp per node ----------------
// phase 0: d_Cb = relu(A * d_A + b1);   phase 1: d_B = A * d_Cb
// All device-global pointers resolved in DEVICE code (host shadow is a trap).
__global__ __launch_bounds__(256) void k_gather(const float* __restrict__ b1,
                                                int phase) {
    int node = (blockIdx.x * 256 + threadIdx.x) >> 5;
    if (node >= NN) return;
    int lane = threadIdx.x & 31;
    const float* __restrict__ src = phase ? d_Cb : d_A;
    float* __restrict__ dst       = phase ? d_B  : d_Cb;
    int beg = d_off[node], end = d_off[node + 1];
    float dc = d_dis[node];

    float4 acc = ((const float4*)(src + (size_t)node * CH))[lane];
    acc.x *= dc; acc.y *= dc; acc.z *= dc; acc.w *= dc;

    for (int base = beg; base < end; base += 32) {
        int t = base + lane;
        int2 pr = (t < end) ? d_adj[t] : make_int2(0, 0);
        int n = min(32, end - base);
#pragma unroll 4
        for (int k = 0; k < n; k++) {
            int   j = __shfl_sync(0xffffffffu, pr.x, k);
            float w = __int_as_float(__shfl_sync(0xffffffffu, pr.y, k));
            float4 v = ((const float4*)(src + (size_t)j * CH))[lane];
            acc.x = fmaf(w, v.x, acc.x);
            acc.y = fmaf(w, v.y, acc.y);
            acc.z = fmaf(w, v.z, acc.z);
            acc.w = fmaf(w, v.w, acc.w);
        }
    }
    acc.x *= dc; acc.y *= dc; acc.z *= dc; acc.w *= dc;

    if (phase == 0) {
        float4 bias = ((const float4*)b1)[lane];
        acc.x = fmaxf(acc.x + bias.x, 0.f);
        acc.y = fmaxf(acc.y + bias.y, 0.f);
        acc.z = fmaxf(acc.z + bias.z, 0.f);
        acc.w = fmaxf(acc.w + bias.w, 0.f);
    }
    ((float4*)(dst + (size_t)node * CH))[lane] = acc;
}

// ---------------- fused epilogue: mu/lv GEMMs + reparam ----------------
__global__ __launch_bounds__(256) void k_final(const float* __restrict__ Wmu,
                                               const float* __restrict__ bmu,
                                               const float* __restrict__ Wlv,
                                               const float* __restrict__ blv,
                                               const float* __restrict__ eps,
                                               float* __restrict__ out) {
    __shared__ float sG[32][36];
    __shared__ float sMu[32 * LAT];
    __shared__ float sLv[32 * LAT];
    int tid  = threadIdx.x;
    int row0 = blockIdx.x * 32;
    int nl = tid >> 3, colg = tid & 7;
    int lr = tid >> 3, lc = (tid & 7) * 4;
    int lnode = row0 + lr;

    float mu[8] = {0,0,0,0,0,0,0,0};
    float lv[8] = {0,0,0,0,0,0,0,0};

    for (int kc = 0; kc < CH; kc += 32) {
        float4 g = *(const float4*)(d_B + (size_t)lnode * CH + kc + lc);
        *(float4*)&sG[lr][lc] = g;
        const float4* Wm4 = (const float4*)(Wmu + (size_t)kc * LAT);
        const float4* Wl4 = (const float4*)(Wlv + (size_t)kc * LAT);
        ((float4*)sMu)[tid]       = Wm4[tid];
        ((float4*)sMu)[tid + 256] = Wm4[tid + 256];
        ((float4*)sLv)[tid]       = Wl4[tid];
        ((float4*)sLv)[tid + 256] = Wl4[tid + 256];
        __syncthreads();
#pragma unroll
        for (int k = 0; k < 32; k++) {
            float a = sG[nl][k];
            float4 m0 = *(const float4*)&sMu[k * LAT + colg * 4];
            float4 m1 = *(const float4*)&sMu[k * LAT + 32 + colg * 4];
            float4 l0 = *(const float4*)&sLv[k * LAT + colg * 4];
            float4 l1 = *(const float4*)&sLv[k * LAT + 32 + colg * 4];
            mu[0] += a * m0.x; mu[1] += a * m0.y; mu[2] += a * m0.z; mu[3] += a * m0.w;
            mu[4] += a * m1.x; mu[5] += a * m1.y; mu[6] += a * m1.z; mu[7] += a * m1.w;
            lv[0] += a * l0.x; lv[1] += a * l0.y; lv[2] += a * l0.z; lv[3] += a * l0.w;
            lv[4] += a * l1.x; lv[5] += a * l1.y; lv[6] += a * l1.z; lv[7] += a * l1.w;
        }
        __syncthreads();
    }

    int node = row0 + nl;
    float* out_z  = out;
    float* out_mu = out + (size_t)NN * LAT;
    float* out_lv = out + 2 * (size_t)NN * LAT;
#pragma unroll
    for (int h = 0; h < 2; h++) {
        int c0 = h * 32 + colg * 4;
        float4 bm = *(const float4*)(bmu + c0);
        float4 bl = *(const float4*)(blv + c0);
        float4 ev = *(const float4*)(eps + (size_t)node * LAT + c0);
        float m0 = mu[h*4+0] + bm.x, m1 = mu[h*4+1] + bm.y,
              m2 = mu[h*4+2] + bm.z, m3 = mu[h*4+3] + bm.w;
        float l0 = lv[h*4+0] + bl.x, l1 = lv[h*4+1] + bl.y,
              l2 = lv[h*4+2] + bl.z, l3 = lv[h*4+3] + bl.w;
        float z0 = m0 + ev.x * expf(0.5f * l0);
        float z1 = m1 + ev.y * expf(0.5f * l1);
        float z2 = m2 + ev.z * expf(0.5f * l2);
        float z3 = m3 + ev.w * expf(0.5f * l3);
        size_t o = (size_t)node * LAT + c0;
        *(float4*)(out_mu + o) = make_float4(m0, m1, m2, m3);
        *(float4*)(out_lv + o) = make_float4(l0, l1, l2, l3);
        *(float4*)(out_z  + o) = make_float4(z0, z1, z2, z3);
    }
}

// ---------------- launch ----------------
extern "C" void kernel_launch(void* const* d_in, const int* in_sizes, int n_in,
                              void* d_out, int out_size) {
    const float* x   = (const float*)d_in[0];
    const void*  ei  = d_in[1];
    const float* W1  = (const float*)d_in[2];
    const float* b1  = (const float*)d_in[3];
    const float* Wmu = (const float*)d_in[4];
    const float* bmu = (const float*)d_in[5];
    const float* Wlv = (const float*)d_in[6];
    const float* blv = (const float*)d_in[7];
    const float* eps = (const float*)d_in[8];
    float* out = (float*)d_out;

    k_detect<<<1, 256>>>((const int*)ei);
    k_zero_cnt<<<(NN + 255) / 256, 256>>>();
    k_hist<<<(NE + 255) / 256, 256>>>(ei);
    k_dis2<<<(NN + 255) / 256, 256>>>();
    k_scan_local<<<NBLK_SCAN, 1024>>>();
    k_scan_blk<<<1, 128>>>();
    k_scan_add<<<NBLK_SCAN, 1024>>>();
    k_fill<<<(NE + 255) / 256, 256>>>(ei);

    k_gemm1<<<NN / 32, 256>>>(x, W1);                 // d_A = x @ W1

    k_gather<<<(NN * 32 + 255) / 256, 256>>>(b1, 0);  // d_Cb = relu(A d_A + b1)
    k_gather<<<(NN * 32 + 255) / 256, 256>>>(b1, 1);  // d_B  = A d_Cb

    k_final<<<NN / 32, 256>>>(Wmu, bmu, Wlv, blv, eps, out);
}

// round 4
// speedup vs baseline: 1.5810x; 1.0140x over previous
#include <cuda_runtime.h>

#define NN  100000
#define NE  1600000
#define CH  128
#define LAT 64
#define NBLK_SCAN 98      // ceil(100000/1024)
#define NTILE     3125    // NN/32 gemm row tiles
#define TILES_A   1563
#define TILES_B   (NTILE - TILES_A)
#define NHIST     512
#define NFILL     1024

// ---------------- scratch (no allocations allowed) ----------------
__device__ float d_A[(size_t)NN * CH];   // h0 = x @ W1
__device__ float d_B[(size_t)NN * CH];   // g = A * h
__device__ float d_Cb[(size_t)NN * CH];  // h = relu(conv1)
__device__ float d_dis[NN];
__device__ int   d_cnt[NN];
__device__ int   d_off[NN + 1];
__device__ int   d_pos[NN];
__device__ int2  d_adj[NE];              // {src_idx, bitcast(dis[src])}
__device__ int   d_blk[128], d_blkoff[128];
__device__ int   d_is64;

// ---------------- detect width + zero counters (fused) ----------------
__global__ void k_detect_zero(const int* __restrict__ ei32) {
    int gid = blockIdx.x * 256 + threadIdx.x;
    if (gid < NN) d_cnt[gid] = 0;
    if (blockIdx.x == 0) {
        __shared__ int any;
        if (threadIdx.x == 0) any = 0;
        __syncthreads();
        for (int i = threadIdx.x; i < 4096; i += 256)
            if (ei32[2 * i + 1] != 0) any = 1;
        __syncthreads();
        if (threadIdx.x == 0) d_is64 = (any == 0) ? 1 : 0;
    }
}

__device__ __forceinline__ int edge_idx(const void* ei, int part, int e) {
    if (d_is64) return (int)((const long long*)ei)[(size_t)part * NE + e];
    return ((const int*)ei)[(size_t)part * NE + e];
}

// ---------------- GEMM tile body (32 rows of d_A = x @ W1) ----------------
__device__ __forceinline__ void gemm_tile(const float* __restrict__ x,
                                          const float* __restrict__ W,
                                          int tile) {
    __shared__ float sX[32][36];
    __shared__ float sW[32][CH];
    int tid  = threadIdx.x;
    int row0 = tile * 32;
    int rg = tid >> 4, cg = tid & 15;
    int lr = tid >> 3, lc = (tid & 7) * 4;

    float a0c[8] = {0,0,0,0,0,0,0,0};
    float a1c[8] = {0,0,0,0,0,0,0,0};

    for (int kc = 0; kc < CH; kc += 32) {
        float4 xv = *(const float4*)(x + (size_t)(row0 + lr) * CH + kc + lc);
        *(float4*)&sX[lr][lc] = xv;
        const float4* W4 = (const float4*)(W + (size_t)kc * CH);
        float4* sW4 = (float4*)sW;
#pragma unroll
        for (int i = 0; i < 4; i++) sW4[tid + i * 256] = W4[tid + i * 256];
        __syncthreads();
#pragma unroll
        for (int k = 0; k < 32; k++) {
            float a0 = sX[rg * 2][k];
            float a1 = sX[rg * 2 + 1][k];
            float4 w0 = *(const float4*)&sW[k][cg * 4];
            float4 w1 = *(const float4*)&sW[k][64 + cg * 4];
            a0c[0] += a0 * w0.x; a0c[1] += a0 * w0.y; a0c[2] += a0 * w0.z; a0c[3] += a0 * w0.w;
            a0c[4] += a0 * w1.x; a0c[5] += a0 * w1.y; a0c[6] += a0 * w1.z; a0c[7] += a0 * w1.w;
            a1c[0] += a1 * w0.x; a1c[1] += a1 * w0.y; a1c[2] += a1 * w0.z; a1c[3] += a1 * w0.w;
            a1c[4] += a1 * w1.x; a1c[5] += a1 * w1.y; a1c[6] += a1 * w1.z; a1c[7] += a1 * w1.w;
        }
        __syncthreads();
    }
    size_t r = (size_t)(row0 + rg * 2);
    *(float4*)&d_A[r * CH + cg * 4]            = make_float4(a0c[0], a0c[1], a0c[2], a0c[3]);
    *(float4*)&d_A[r * CH + 64 + cg * 4]       = make_float4(a0c[4], a0c[5], a0c[6], a0c[7]);
    *(float4*)&d_A[(r + 1) * CH + cg * 4]      = make_float4(a1c[0], a1c[1], a1c[2], a1c[3]);
    *(float4*)&d_A[(r + 1) * CH + 64 + cg * 4] = make_float4(a1c[4], a1c[5], a1c[6], a1c[7]);
}

// ---------------- kernel A: hist blocks ∥ gemm tiles 0..TILES_A ----------------
__global__ __launch_bounds__(256) void k_hist_gemm(const void* __restrict__ ei,
                                                   const float* __restrict__ x,
                                                   const float* __restrict__ W) {
    if (blockIdx.x < NHIST) {
        for (int i = blockIdx.x * 256 + threadIdx.x; i < NE; i += NHIST * 256)
            atomicAdd(&d_cnt[edge_idx(ei, 1, i)], 1);
        return;
    }
    gemm_tile(x, W, blockIdx.x - NHIST);
}

// ---------------- kernel B: fill blocks ∥ gemm tiles TILES_A..NTILE ----------------
__global__ __launch_bounds__(256) void k_fill_gemm(const void* __restrict__ ei,
                                                   const float* __restrict__ x,
                                                   const float* __restrict__ W) {
    if (blockIdx.x < NFILL) {
        for (int e = blockIdx.x * 256 + threadIdx.x; e < NE; e += NFILL * 256) {
            int r = edge_idx(ei, 0, e);
            int c = edge_idx(ei, 1, e);
            int p = atomicAdd(&d_pos[c], 1);
            d_adj[p] = make_int2(r, __float_as_int(d_dis[r]));
        }
        return;
    }
    gemm_tile(x, W, TILES_A + blockIdx.x - NFILL);
}

// ---------------- prefix sum (dis fused into first stage) ----------------
__global__ void k_scan_local() {
    __shared__ int s[1024];
    int tid = threadIdx.x;
    int gid = blockIdx.x * 1024 + tid;
    int v = (gid < NN) ? d_cnt[gid] : 0;
    if (gid < NN) d_dis[gid] = rsqrtf((float)v + 1.0f);   // +1 self loop
    s[tid] = v;
    __syncthreads();
    for (int o = 1; o < 1024; o <<= 1) {
        int t = (tid >= o) ? s[tid - o] : 0;
        __syncthreads();
        s[tid] += t;
        __syncthreads();
    }
    if (gid < NN) d_off[gid] = s[tid] - v;
    if (tid == 1023) d_blk[blockIdx.x] = s[1023];
}
__global__ void k_scan_blk() {
    __shared__ int s[128];
    int tid = threadIdx.x;
    int v = (tid < NBLK_SCAN) ? d_blk[tid] : 0;
    s[tid] = v;
    __syncthreads();
    for (int o = 1; o < 128; o <<= 1) {
        int t = (tid >= o) ? s[tid - o] : 0;
        __syncthreads();
        s[tid] += t;
        __syncthreads();
    }
    d_blkoff[tid] = s[tid] - v;
}
__global__ void k_scan_add() {
    int gid = blockIdx.x * 1024 + threadIdx.x;
    if (gid < NN) {
        int o = d_off[gid] + d_blkoff[blockIdx.x];
        d_off[gid] = o;
        d_pos[gid] = o;
    }
    if (gid == 0) d_off[NN] = NE;
}

// ---------------- CSR gather: one warp per node ----------------
__global__ __launch_bounds__(256) void k_gather(const float* __restrict__ b1,
                                                int phase) {
    int node = (blockIdx.x * 256 + threadIdx.x) >> 5;
    if (node >= NN) return;
    int lane = threadIdx.x & 31;
    const float* __restrict__ src = phase ? d_Cb : d_A;
    float* __restrict__ dst       = phase ? d_B  : d_Cb;
    int beg = d_off[node], end = d_off[node + 1];
    float dc = d_dis[node];

    float4 acc = ((const float4*)(src + (size_t)node * CH))[lane];
    acc.x *= dc; acc.y *= dc; acc.z *= dc; acc.w *= dc;

    for (int base = beg; base < end; base += 32) {
        int t = base + lane;
        int2 pr = (t < end) ? d_adj[t] : make_int2(0, 0);
        int n = min(32, end - base);
#pragma unroll 8
        for (int k = 0; k < n; k++) {
            int   j = __shfl_sync(0xffffffffu, pr.x, k);
            float w = __int_as_float(__shfl_sync(0xffffffffu, pr.y, k));
            float4 v = ((const float4*)(src + (size_t)j * CH))[lane];
            acc.x = fmaf(w, v.x, acc.x);
            acc.y = fmaf(w, v.y, acc.y);
            acc.z = fmaf(w, v.z, acc.z);
            acc.w = fmaf(w, v.w, acc.w);
        }
    }
    acc.x *= dc; acc.y *= dc; acc.z *= dc; acc.w *= dc;

    if (phase == 0) {
        float4 bias = ((const float4*)b1)[lane];
        acc.x = fmaxf(acc.x + bias.x, 0.f);
        acc.y = fmaxf(acc.y + bias.y, 0.f);
        acc.z = fmaxf(acc.z + bias.z, 0.f);
        acc.w = fmaxf(acc.w + bias.w, 0.f);
    }
    ((float4*)(dst + (size_t)node * CH))[lane] = acc;
}

// ---------------- fused epilogue: mu/lv GEMMs + reparam ----------------
__global__ __launch_bounds__(256) void k_final(const float* __restrict__ Wmu,
                                               const float* __restrict__ bmu,
                                               const float* __restrict__ Wlv,
                                               const float* __restrict__ blv,
                                               const float* __restrict__ eps,
                                               float* __restrict__ out) {
    __shared__ float sG[32][36];
    __shared__ float sMu[32 * LAT];
    __shared__ float sLv[32 * LAT];
    int tid  = threadIdx.x;
    int row0 = blockIdx.x * 32;
    int nl = tid >> 3, colg = tid & 7;
    int lr = tid >> 3, lc = (tid & 7) * 4;
    int lnode = row0 + lr;

    float mu[8] = {0,0,0,0,0,0,0,0};
    float lv[8] = {0,0,0,0,0,0,0,0};

    for (int kc = 0; kc < CH; kc += 32) {
        float4 g = *(const float4*)(d_B + (size_t)lnode * CH + kc + lc);
        *(float4*)&sG[lr][lc] = g;
        const float4* Wm4 = (const float4*)(Wmu + (size_t)kc * LAT);
        const float4* Wl4 = (const float4*)(Wlv + (size_t)kc * LAT);
        ((float4*)sMu)[tid]       = Wm4[tid];
        ((float4*)sMu)[tid + 256] = Wm4[tid + 256];
        ((float4*)sLv)[tid]       = Wl4[tid];
        ((float4*)sLv)[tid + 256] = Wl4[tid + 256];
        __syncthreads();
#pragma unroll
        for (int k = 0; k < 32; k++) {
            float a = sG[nl][k];
            float4 m0 = *(const float4*)&sMu[k * LAT + colg * 4];
            float4 m1 = *(const float4*)&sMu[k * LAT + 32 + colg * 4];
            float4 l0 = *(const float4*)&sLv[k * LAT + colg * 4];
            float4 l1 = *(const float4*)&sLv[k * LAT + 32 + colg * 4];
            mu[0] += a * m0.x; mu[1] += a * m0.y; mu[2] += a * m0.z; mu[3] += a * m0.w;
            mu[4] += a * m1.x; mu[5] += a * m1.y; mu[6] += a * m1.z; mu[7] += a * m1.w;
            lv[0] += a * l0.x; lv[1] += a * l0.y; lv[2] += a * l0.z; lv[3] += a * l0.w;
            lv[4] += a * l1.x; lv[5] += a * l1.y; lv[6] += a * l1.z; lv[7] += a * l1.w;
        }
        __syncthreads();
    }

    int node = row0 + nl;
    float* out_z  = out;
    float* out_mu = out + (size_t)NN * LAT;
    float* out_lv = out + 2 * (size_t)NN * LAT;
#pragma unroll
    for (int h = 0; h < 2; h++) {
        int c0 = h * 32 + colg * 4;
        float4 bm = *(const float4*)(bmu + c0);
        float4 bl = *(const float4*)(blv + c0);
        float4 ev = *(const float4*)(eps + (size_t)node * LAT + c0);
        float m0 = mu[h*4+0] + bm.x, m1 = mu[h*4+1] + bm.y,
              m2 = mu[h*4+2] + bm.z, m3 = mu[h*4+3] + bm.w;
        float l0 = lv[h*4+0] + bl.x, l1 = lv[h*4+1] + bl.y,
              l2 = lv[h*4+2] + bl.z, l3 = lv[h*4+3] + bl.w;
        float z0 = m0 + ev.x * expf(0.5f * l0);
        float z1 = m1 + ev.y * expf(0.5f * l1);
        float z2 = m2 + ev.z * expf(0.5f * l2);
        float z3 = m3 + ev.w * expf(0.5f * l3);
        size_t o = (size_t)node * LAT + c0;
        *(float4*)(out_mu + o) = make_float4(m0, m1, m2, m3);
        *(float4*)(out_lv + o) = make_float4(l0, l1, l2, l3);
        *(float4*)(out_z  + o) = make_float4(z0, z1, z2, z3);
    }
}

// ---------------- launch ----------------
extern "C" void kernel_launch(void* const* d_in, const int* in_sizes, int n_in,
                              void* d_out, int out_size) {
    const float* x   = (const float*)d_in[0];
    const void*  ei  = d_in[1];
    const float* W1  = (const float*)d_in[2];
    const float* b1  = (const float*)d_in[3];
    const float* Wmu = (const float*)d_in[4];
    const float* bmu = (const float*)d_in[5];
    const float* Wlv = (const float*)d_in[6];
    const float* blv = (const float*)d_in[7];
    const float* eps = (const float*)d_in[8];
    float* out = (float*)d_out;

    k_detect_zero<<<(NN + 255) / 256, 256>>>((const int*)ei);
    k_hist_gemm<<<NHIST + TILES_A, 256>>>(ei, x, W1);   // hist ∥ gemm lower half
    k_scan_local<<<NBLK_SCAN, 1024>>>();                // + dis
    k_scan_blk<<<1, 128>>>();
    k_scan_add<<<NBLK_SCAN, 1024>>>();
    k_fill_gemm<<<NFILL + TILES_B, 256>>>(ei, x, W1);   // fill ∥ gemm upper half

    k_gather<<<(NN * 32 + 255) / 256, 256>>>(b1, 0);    // d_Cb = relu(A d_A + b1)
    k_gather<<<(NN * 32 + 255) / 256, 256>>>(b1, 1);    // d_B  = A d_Cb

    k_final<<<NN / 32, 256>>>(Wmu, bmu, Wlv, blv, eps, out);
}

// round 5
// speedup vs baseline: 2.1693x; 1.3721x over previous
#include <cuda_runtime.h>
#include <cstdint>

#define NN  100000
#define NE  1600000
#define CH  128
#define LAT 64
#define NBLK_SCAN 98      // ceil(100000/1024)
#define GBLK 782          // ceil(NN/128) gemm blocks

// ---------------- scratch (no allocations allowed) ----------------
__device__ float d_A[(size_t)NN * CH];   // h0 = x @ W1
__device__ float d_B[(size_t)NN * CH];   // g = A * h
__device__ float d_Cb[(size_t)NN * CH];  // h = relu(conv1)
__device__ float d_dis[NN];
__device__ int   d_cnt[NN];
__device__ int   d_off[NN + 1];
__device__ int   d_pos[NN];
__device__ int2  d_adj[NE];
__device__ int   d_blk[128], d_blkoff[128];
__device__ int   d_is64;
__device__ float d_W1hi[CH * CH], d_W1lo[CH * CH];     // tf32 split of W1
__device__ float d_Wmlhi[CH * CH], d_Wmllo[CH * CH];   // tf32 split of [Wmu|Wlv]

// ---------------- tf32 helpers ----------------
__device__ __forceinline__ uint32_t f2tf32(float v) {
    uint32_t r; asm("cvt.rna.tf32.f32 %0, %1;" : "=r"(r) : "f"(v)); return r;
}
__device__ __forceinline__ void split_tf32(float v, uint32_t& hi, uint32_t& lo) {
    hi = f2tf32(v);
    lo = f2tf32(v - __uint_as_float(hi));
}
__device__ __forceinline__ void mma_tf32(float c[4], const uint32_t a[4],
                                         uint32_t b0, uint32_t b1) {
    asm volatile(
        "mma.sync.aligned.m16n8k8.row.col.f32.tf32.tf32.f32 "
        "{%0,%1,%2,%3},{%4,%5,%6,%7},{%8,%9},{%0,%1,%2,%3};"
        : "+f"(c[0]), "+f"(c[1]), "+f"(c[2]), "+f"(c[3])
        : "r"(a[0]), "r"(a[1]), "r"(a[2]), "r"(a[3]), "r"(b0), "r"(b1));
}

// ---------------- W split (one-time per call, tiny) ----------------
__global__ void k_wsplit(const float* __restrict__ W1,
                         const float* __restrict__ Wmu,
                         const float* __restrict__ Wlv) {
    int i = blockIdx.x * 256 + threadIdx.x;
    if (i >= CH * CH) return;
    uint32_t h, l;
    split_tf32(W1[i], h, l);
    d_W1hi[i] = __uint_as_float(h);
    d_W1lo[i] = __uint_as_float(l);
    int k = i >> 7, n = i & 127;
    float w = (n < 64) ? Wmu[k * 64 + n] : Wlv[k * 64 + (n - 64)];
    split_tf32(w, h, l);
    d_Wmlhi[i] = __uint_as_float(h);
    d_Wmllo[i] = __uint_as_float(l);
}

// ---------------- detect width + zero counters ----------------
__global__ void k_detect_zero(const int* __restrict__ ei32) {
    int gid = blockIdx.x * 256 + threadIdx.x;
    if (gid < NN) d_cnt[gid] = 0;
    if (blockIdx.x == 0) {
        __shared__ int any;
        if (threadIdx.x == 0) any = 0;
        __syncthreads();
        for (int i = threadIdx.x; i < 4096; i += 256)
            if (ei32[2 * i + 1] != 0) any = 1;
        __syncthreads();
        if (threadIdx.x == 0) d_is64 = (any == 0) ? 1 : 0;
    }
}
__device__ __forceinline__ int edge_idx(const void* ei, int part, int e) {
    if (d_is64) return (int)((const long long*)ei)[(size_t)part * NE + e];
    return ((const int*)ei)[(size_t)part * NE + e];
}

__global__ void k_hist(const void* __restrict__ ei) {
    int i = blockIdx.x * 256 + threadIdx.x;
    if (i < NE) atomicAdd(&d_cnt[edge_idx(ei, 1, i)], 1);
}

// ---------------- shared 3xTF32 GEMM mainloop: 128 rows x 128 cols, K=128 ----
// acc[j][q]: ntile j covers cols 8j..8j+7; warp covers rows warp*16..+15.
__device__ __forceinline__ void gemm_tc_loop(const float* __restrict__ Asrc,
                                             const float* __restrict__ Whi,
                                             const float* __restrict__ Wlo,
                                             int row0, float acc[16][4]) {
    __shared__ float sA[128 * 36];
    __shared__ float sBh[32 * 132];
    __shared__ float sBl[32 * 132];
    int tid  = threadIdx.x;
    int lane = tid & 31, warp = tid >> 5;
    int g = lane >> 2, tig = lane & 3;

    for (int kc = 0; kc < CH; kc += 32) {
#pragma unroll
        for (int i = 0; i < 4; i++) {           // A tile 128x32
            int idx = tid + i * 256;
            int r = idx >> 3, c4 = (idx & 7) * 4;
            int rg = row0 + r; rg = (rg < NN) ? rg : (NN - 1);
            float4 v = *(const float4*)(Asrc + (size_t)rg * CH + kc + c4);
            *(float4*)(sA + r * 36 + c4) = v;
        }
#pragma unroll
        for (int i = 0; i < 4; i++) {           // B chunks 32x128 (hi+lo)
            int idx = tid + i * 256;
            int r = idx >> 5, c4 = (idx & 31) * 4;
            *(float4*)(sBh + r * 132 + c4) = *(const float4*)(Whi + (size_t)(kc + r) * CH + c4);
            *(float4*)(sBl + r * 132 + c4) = *(const float4*)(Wlo + (size_t)(kc + r) * CH + c4);
        }
        __syncthreads();
#pragma unroll
        for (int ks = 0; ks < 4; ks++) {
            int k0 = ks * 8;
            int ar = warp * 16 + g;
            uint32_t ah[4], al[4];
            split_tf32(sA[ar * 36 + k0 + tig],           ah[0], al[0]);
            split_tf32(sA[(ar + 8) * 36 + k0 + tig],     ah[1], al[1]);
            split_tf32(sA[ar * 36 + k0 + tig + 4],       ah[2], al[2]);
            split_tf32(sA[(ar + 8) * 36 + k0 + tig + 4], ah[3], al[3]);
#pragma unroll
            for (int j = 0; j < 16; j++) {
                uint32_t bh0 = __float_as_uint(sBh[(k0 + tig) * 132 + j * 8 + g]);
                uint32_t bh1 = __float_as_uint(sBh[(k0 + tig + 4) * 132 + j * 8 + g]);
                uint32_t bl0 = __float_as_uint(sBl[(k0 + tig) * 132 + j * 8 + g]);
                uint32_t bl1 = __float_as_uint(sBl[(k0 + tig + 4) * 132 + j * 8 + g]);
                mma_tf32(acc[j], ah, bh0, bh1);
                mma_tf32(acc[j], ah, bl0, bl1);
                mma_tf32(acc[j], al, bh0, bh1);
            }
        }
        __syncthreads();
    }
}

// ---------------- GEMM1: d_A = x @ W1 (tensor cores) ----------------
__global__ __launch_bounds__(256) void k_gemm1_tc(const float* __restrict__ x) {
    float acc[16][4];
#pragma unroll
    for (int j = 0; j < 16; j++) acc[j][0] = acc[j][1] = acc[j][2] = acc[j][3] = 0.f;
    int row0 = blockIdx.x * 128;
    gemm_tc_loop(x, d_W1hi, d_W1lo, row0, acc);

    int lane = threadIdx.x & 31, warp = threadIdx.x >> 5;
    int g = lane >> 2, tig = lane & 3;
    int r0 = row0 + warp * 16 + g, r1 = r0 + 8;
#pragma unroll
    for (int j = 0; j < 16; j++) {
        int col = j * 8 + 2 * tig;
        if (r0 < NN) *(float2*)(d_A + (size_t)r0 * CH + col) = make_float2(acc[j][0], acc[j][1]);
        if (r1 < NN) *(float2*)(d_A + (size_t)r1 * CH + col) = make_float2(acc[j][2], acc[j][3]);
    }
}

// ---------------- prefix sum (dis fused) ----------------
__global__ void k_scan_local() {
    __shared__ int s[1024];
    int tid = threadIdx.x;
    int gid = blockIdx.x * 1024 + tid;
    int v = (gid < NN) ? d_cnt[gid] : 0;
    if (gid < NN) d_dis[gid] = rsqrtf((float)v + 1.0f);
    s[tid] = v;
    __syncthreads();
    for (int o = 1; o < 1024; o <<= 1) {
        int t = (tid >= o) ? s[tid - o] : 0;
        __syncthreads();
        s[tid] += t;
        __syncthreads();
    }
    if (gid < NN) d_off[gid] = s[tid] - v;
    if (tid == 1023) d_blk[blockIdx.x] = s[1023];
}
__global__ void k_scan_blk() {
    __shared__ int s[128];
    int tid = threadIdx.x;
    int v = (tid < NBLK_SCAN) ? d_blk[tid] : 0;
    s[tid] = v;
    __syncthreads();
    for (int o = 1; o < 128; o <<= 1) {
        int t = (tid >= o) ? s[tid - o] : 0;
        __syncthreads();
        s[tid] += t;
        __syncthreads();
    }
    d_blkoff[tid] = s[tid] - v;
}
__global__ void k_scan_add() {
    int gid = blockIdx.x * 1024 + threadIdx.x;
    if (gid < NN) {
        int o = d_off[gid] + d_blkoff[blockIdx.x];
        d_off[gid] = o;
        d_pos[gid] = o;
    }
    if (gid == 0) d_off[NN] = NE;
}

__global__ void k_fill(const void* __restrict__ ei) {
    int e = blockIdx.x * 256 + threadIdx.x;
    if (e >= NE) return;
    int r = edge_idx(ei, 0, e);
    int c = edge_idx(ei, 1, e);
    int p = atomicAdd(&d_pos[c], 1);
    d_adj[p] = make_int2(r, __float_as_int(d_dis[r]));
}

// ---------------- CSR gather: one warp per node ----------------
__global__ __launch_bounds__(256) void k_gather(const float* __restrict__ b1,
                                                int phase) {
    int node = (blockIdx.x * 256 + threadIdx.x) >> 5;
    if (node >= NN) return;
    int lane = threadIdx.x & 31;
    const float* __restrict__ src = phase ? d_Cb : d_A;
    float* __restrict__ dst       = phase ? d_B  : d_Cb;
    int beg = d_off[node], end = d_off[node + 1];
    float dc = d_dis[node];

    float4 acc = ((const float4*)(src + (size_t)node * CH))[lane];
    acc.x *= dc; acc.y *= dc; acc.z *= dc; acc.w *= dc;

    for (int base = beg; base < end; base += 32) {
        int t = base + lane;
        int2 pr = (t < end) ? d_adj[t] : make_int2(0, 0);
        int n = min(32, end - base);
#pragma unroll 8
        for (int k = 0; k < n; k++) {
            int   j = __shfl_sync(0xffffffffu, pr.x, k);
            float w = __int_as_float(__shfl_sync(0xffffffffu, pr.y, k));
            float4 v = ((const float4*)(src + (size_t)j * CH))[lane];
            acc.x = fmaf(w, v.x, acc.x);
            acc.y = fmaf(w, v.y, acc.y);
            acc.z = fmaf(w, v.z, acc.z);
            acc.w = fmaf(w, v.w, acc.w);
        }
    }
    acc.x *= dc; acc.y *= dc; acc.z *= dc; acc.w *= dc;

    if (phase == 0) {
        float4 bias = ((const float4*)b1)[lane];
        acc.x = fmaxf(acc.x + bias.x, 0.f);
        acc.y = fmaxf(acc.y + bias.y, 0.f);
        acc.z = fmaxf(acc.z + bias.z, 0.f);
        acc.w = fmaxf(acc.w + bias.w, 0.f);
    }
    ((float4*)(dst + (size_t)node * CH))[lane] = acc;
}

// ---------------- final: [mu|lv] = g @ [Wmu|Wlv] (tensor) + reparam ----------
__global__ __launch_bounds__(256) void k_final_tc(const float* __restrict__ bmu,
                                                  const float* __restrict__ blv,
                                                  const float* __restrict__ eps,
                                                  float* __restrict__ out) {
    float acc[16][4];
#pragma unroll
    for (int j = 0; j < 16; j++) acc[j][0] = acc[j][1] = acc[j][2] = acc[j][3] = 0.f;
    int row0 = blockIdx.x * 128;
    gemm_tc_loop(d_B, d_Wmlhi, d_Wmllo, row0, acc);

    int lane = threadIdx.x & 31, warp = threadIdx.x >> 5;
    int g = lane >> 2, tig = lane & 3;
    int r0 = row0 + warp * 16 + g, r1 = r0 + 8;

    float* out_z  = out;
    float* out_mu = out + (size_t)NN * LAT;
    float* out_lv = out + 2 * (size_t)NN * LAT;

#pragma unroll
    for (int j = 0; j < 8; j++) {               // mu tiles; lv = tile j+8
        int col = j * 8 + 2 * tig;
        float2 bm = *(const float2*)(bmu + col);
        float2 bl = *(const float2*)(blv + col);
        // row r0
        if (r0 < NN) {
            float m0 = acc[j][0] + bm.x,     m1 = acc[j][1] + bm.y;
            float l0 = acc[j + 8][0] + bl.x, l1 = acc[j + 8][1] + bl.y;
            float2 ev = *(const float2*)(eps + (size_t)r0 * LAT + col);
            float z0 = m0 + ev.x * expf(0.5f * l0);
            float z1 = m1 + ev.y * expf(0.5f * l1);
            size_t o = (size_t)r0 * LAT + col;
            *(float2*)(out_mu + o) = make_float2(m0, m1);
            *(float2*)(out_lv + o) = make_float2(l0, l1);
            *(float2*)(out_z  + o) = make_float2(z0, z1);
        }
        // row r1
        if (r1 < NN) {
            float m0 = acc[j][2] + bm.x,     m1 = acc[j][3] + bm.y;
            float l0 = acc[j + 8][2] + bl.x, l1 = acc[j + 8][3] + bl.y;
            float2 ev = *(const float2*)(eps + (size_t)r1 * LAT + col);
            float z0 = m0 + ev.x * expf(0.5f * l0);
            float z1 = m1 + ev.y * expf(0.5f * l1);
            size_t o = (size_t)r1 * LAT + col;
            *(float2*)(out_mu + o) = make_float2(m0, m1);
            *(float2*)(out_lv + o) = make_float2(l0, l1);
            *(float2*)(out_z  + o) = make_float2(z0, z1);
        }
    }
}

// ---------------- launch ----------------
extern "C" void kernel_launch(void* const* d_in, const int* in_sizes, int n_in,
                              void* d_out, int out_size) {
    const float* x   = (const float*)d_in[0];
    const void*  ei  = d_in[1];
    const float* W1  = (const float*)d_in[2];
    const float* b1  = (const float*)d_in[3];
    const float* Wmu = (const float*)d_in[4];
    const float* bmu = (const float*)d_in[5];
    const float* Wlv = (const float*)d_in[6];
    const float* blv = (const float*)d_in[7];
    const float* eps = (const float*)d_in[8];
    float* out = (float*)d_out;

    k_wsplit<<<64, 256>>>(W1, Wmu, Wlv);                 // 1
    k_detect_zero<<<(NN + 255) / 256, 256>>>((const int*)ei); // 2
    k_hist<<<(NE + 255) / 256, 256>>>(ei);               // 3
    k_gemm1_tc<<<GBLK, 256>>>(x);                        // 4 (profiled slot)
    k_scan_local<<<NBLK_SCAN, 1024>>>();                 // 5
    k_scan_blk<<<1, 128>>>();                            // 6
    k_scan_add<<<NBLK_SCAN, 1024>>>();                   // 7
    k_fill<<<(NE + 255) / 256, 256>>>(ei);               // 8

    k_gather<<<(NN * 32 + 255) / 256, 256>>>(b1, 0);     // 9
    k_gather<<<(NN * 32 + 255) / 256, 256>>>(b1, 1);     // 10

    k_final_tc<<<GBLK, 256>>>(bmu, blv, eps, out);       // 11
}

// round 6
// speedup vs baseline: 2.2259x; 1.0261x over previous
#include <cuda_runtime.h>
#include <cstdint>

#define NN  100000
#define NE  1600000
#define CH  128
#define LAT 64
#define NBLK_SCAN 98      // ceil(100000/1024)
#define GBLK 782          // ceil(NN/128) gemm blocks

// ---------------- scratch (no allocations allowed) ----------------
__device__ float d_A[(size_t)NN * CH];   // h0 = x @ W1
__device__ float d_B[(size_t)NN * CH];   // g = A * h
__device__ float d_Cb[(size_t)NN * CH];  // h = relu(conv1)
__device__ float d_dis[NN];
__device__ int   d_cnt[NN];
__device__ int   d_off[NN + 1];
__device__ int   d_pos[NN];
__device__ int2  d_adj[NE];
__device__ int   d_blk[128], d_blkoff[128];
__device__ int   d_is64;
// B in per-thread MMA fragment layout: idx = ((kp*16 + j)*32 + lane)*4 + q
// q: {b0(ks=2kp), b1(ks=2kp), b0(ks=2kp+1), b1(ks=2kp+1)}
__device__ float d_F1hi[CH * CH],  d_F1lo[CH * CH];    // W1
__device__ float d_Fmlhi[CH * CH], d_Fmllo[CH * CH];   // [Wmu|Wlv]

// ---------------- tf32 helpers ----------------
__device__ __forceinline__ uint32_t f2tf32(float v) {
    uint32_t r; asm("cvt.rna.tf32.f32 %0, %1;" : "=r"(r) : "f"(v)); return r;
}
__device__ __forceinline__ void split_tf32(float v, uint32_t& hi, uint32_t& lo) {
    hi = f2tf32(v);
    lo = f2tf32(v - __uint_as_float(hi));
}
__device__ __forceinline__ void mma_tf32(float c[4], const uint32_t a[4],
                                         uint32_t b0, uint32_t b1) {
    asm volatile(
        "mma.sync.aligned.m16n8k8.row.col.f32.tf32.tf32.f32 "
        "{%0,%1,%2,%3},{%4,%5,%6,%7},{%8,%9},{%0,%1,%2,%3};"
        : "+f"(c[0]), "+f"(c[1]), "+f"(c[2]), "+f"(c[3])
        : "r"(a[0]), "r"(a[1]), "r"(a[2]), "r"(a[3]), "r"(b0), "r"(b1));
}

// ---------------- W split into fragment layout (one-time, tiny) ----------------
__global__ void k_wsplit(const float* __restrict__ W1,
                         const float* __restrict__ Wmu,
                         const float* __restrict__ Wlv) {
    int i = blockIdx.x * 256 + threadIdx.x;
    if (i >= CH * CH) return;
    int q = i & 3, lane = (i >> 2) & 31, j = (i >> 7) & 15, kp = i >> 11;
    int g = lane >> 2, tig = lane & 3;
    int ks = kp * 2 + (q >> 1);
    int krow = ks * 8 + tig + 4 * (q & 1);
    int col = j * 8 + g;
    uint32_t h, l;
    split_tf32(W1[krow * CH + col], h, l);
    d_F1hi[i] = __uint_as_float(h);
    d_F1lo[i] = __uint_as_float(l);
    float w = (col < 64) ? Wmu[krow * 64 + col] : Wlv[krow * 64 + (col - 64)];
    split_tf32(w, h, l);
    d_Fmlhi[i] = __uint_as_float(h);
    d_Fmllo[i] = __uint_as_float(l);
}

// ---------------- detect width + zero counters ----------------
__global__ void k_detect_zero(const int* __restrict__ ei32) {
    int gid = blockIdx.x * 256 + threadIdx.x;
    if (gid < NN) d_cnt[gid] = 0;
    if (blockIdx.x == 0) {
        __shared__ int any;
        if (threadIdx.x == 0) any = 0;
        __syncthreads();
        for (int i = threadIdx.x; i < 4096; i += 256)
            if (ei32[2 * i + 1] != 0) any = 1;
        __syncthreads();
        if (threadIdx.x == 0) d_is64 = (any == 0) ? 1 : 0;
    }
}
__device__ __forceinline__ int edge_idx(const void* ei, int part, int e) {
    if (d_is64) return (int)((const long long*)ei)[(size_t)part * NE + e];
    return ((const int*)ei)[(size_t)part * NE + e];
}

__global__ void k_hist(const void* __restrict__ ei) {
    int i = blockIdx.x * 256 + threadIdx.x;
    if (i < NE) atomicAdd(&d_cnt[edge_idx(ei, 1, i)], 1);
}

// ---------------- 3xTF32 GEMM mainloop: 128 rows x 128 cols, K=128 ----------
// B consumed as pre-packed fragments via LDS.128; A via swizzled smem.
__device__ __forceinline__ void gemm_tc_loop(const float* __restrict__ Asrc,
                                             const float* __restrict__ Fhi,
                                             const float* __restrict__ Flo,
                                             int row0, float acc[16][4]) {
    __shared__ float  sA[128 * 32];          // XOR-swizzled
    __shared__ float4 sBh[1024];             // frag layout, 2 kp per chunk
    __shared__ float4 sBl[1024];
    int tid  = threadIdx.x;
    int lane = tid & 31, warp = tid >> 5;
    int g = lane >> 2, tig = lane & 3;
    int ar = warp * 16 + g;
    int amask = 4 * g;                       // swizzle mask (ar&7 == g)

    const float4* Fh4 = (const float4*)Fhi;
    const float4* Fl4 = (const float4*)Flo;

    for (int c = 0; c < 4; c++) {            // K chunk = 32
#pragma unroll
        for (int i = 0; i < 4; i++) {        // stage A tile 128x32, swizzled
            int idx = tid + i * 256;
            int r = idx >> 3, c4 = (idx & 7) * 4;
            int rg = row0 + r; rg = (rg < NN) ? rg : (NN - 1);
            float4 v = *(const float4*)(Asrc + (size_t)rg * CH + c * 32 + c4);
            *(float4*)(sA + r * 32 + (c4 ^ ((r & 7) * 4))) = v;
        }
#pragma unroll
        for (int i = 0; i < 4; i++) {        // stage B frags (coalesced copy)
            int t = tid + i * 256;           // 1024 float4 per array per chunk
            int kpl = t >> 9, jj = (t >> 5) & 15, ln = t & 31;
            int sidx = (jj * 2 + kpl) * 32 + ln;
            sBh[sidx] = Fh4[c * 1024 + t];
            sBl[sidx] = Fl4[c * 1024 + t];
        }
        __syncthreads();
#pragma unroll
        for (int kpl = 0; kpl < 2; kpl++) {
            int k0 = kpl * 16;
            uint32_t ah0[4], al0[4], ah1[4], al1[4];
            split_tf32(sA[ar * 32 + ((k0 + tig) ^ amask)],           ah0[0], al0[0]);
            split_tf32(sA[(ar + 8) * 32 + ((k0 + tig) ^ amask)],     ah0[1], al0[1]);
            split_tf32(sA[ar * 32 + ((k0 + tig + 4) ^ amask)],       ah0[2], al0[2]);
            split_tf32(sA[(ar + 8) * 32 + ((k0 + tig + 4) ^ amask)], ah0[3], al0[3]);
            split_tf32(sA[ar * 32 + ((k0 + 8 + tig) ^ amask)],           ah1[0], al1[0]);
            split_tf32(sA[(ar + 8) * 32 + ((k0 + 8 + tig) ^ amask)],     ah1[1], al1[1]);
            split_tf32(sA[ar * 32 + ((k0 + 8 + tig + 4) ^ amask)],       ah1[2], al1[2]);
            split_tf32(sA[(ar + 8) * 32 + ((k0 + 8 + tig + 4) ^ amask)], ah1[3], al1[3]);
#pragma unroll
            for (int j = 0; j < 16; j++) {
                float4 bh = sBh[(j * 2 + kpl) * 32 + lane];
                float4 bl = sBl[(j * 2 + kpl) * 32 + lane];
                mma_tf32(acc[j], ah0, __float_as_uint(bh.x), __float_as_uint(bh.y));
                mma_tf32(acc[j], ah0, __float_as_uint(bl.x), __float_as_uint(bl.y));
                mma_tf32(acc[j], al0, __float_as_uint(bh.x), __float_as_uint(bh.y));
                mma_tf32(acc[j], ah1, __float_as_uint(bh.z), __float_as_uint(bh.w));
                mma_tf32(acc[j], ah1, __float_as_uint(bl.z), __float_as_uint(bl.w));
                mma_tf32(acc[j], al1, __float_as_uint(bh.z), __float_as_uint(bh.w));
            }
        }
        __syncthreads();
    }
}

// ---------------- GEMM1: d_A = x @ W1 (tensor cores) ----------------
__global__ __launch_bounds__(256) void k_gemm1_tc(const float* __restrict__ x) {
    float acc[16][4];
#pragma unroll
    for (int j = 0; j < 16; j++) acc[j][0] = acc[j][1] = acc[j][2] = acc[j][3] = 0.f;
    int row0 = blockIdx.x * 128;
    gemm_tc_loop(x, d_F1hi, d_F1lo, row0, acc);

    int lane = threadIdx.x & 31, warp = threadIdx.x >> 5;
    int g = lane >> 2, tig = lane & 3;
    int r0 = row0 + warp * 16 + g, r1 = r0 + 8;
#pragma unroll
    for (int j = 0; j < 16; j++) {
        int col = j * 8 + 2 * tig;
        if (r0 < NN) *(float2*)(d_A + (size_t)r0 * CH + col) = make_float2(acc[j][0], acc[j][1]);
        if (r1 < NN) *(float2*)(d_A + (size_t)r1 * CH + col) = make_float2(acc[j][2], acc[j][3]);
    }
}

// ---------------- prefix sum (dis fused) ----------------
__global__ void k_scan_local() {
    __shared__ int s[1024];
    int tid = threadIdx.x;
    int gid = blockIdx.x * 1024 + tid;
    int v = (gid < NN) ? d_cnt[gid] : 0;
    if (gid < NN) d_dis[gid] = rsqrtf((float)v + 1.0f);
    s[tid] = v;
    __syncthreads();
    for (int o = 1; o < 1024; o <<= 1) {
        int t = (tid >= o) ? s[tid - o] : 0;
        __syncthreads();
        s[tid] += t;
        __syncthreads();
    }
    if (gid < NN) d_off[gid] = s[tid] - v;
    if (tid == 1023) d_blk[blockIdx.x] = s[1023];
}
__global__ void k_scan_blk() {
    __shared__ int s[128];
    int tid = threadIdx.x;
    int v = (tid < NBLK_SCAN) ? d_blk[tid] : 0;
    s[tid] = v;
    __syncthreads();
    for (int o = 1; o < 128; o <<= 1) {
        int t = (tid >= o) ? s[tid - o] : 0;
        __syncthreads();
        s[tid] += t;
        __syncthreads();
    }
    d_blkoff[tid] = s[tid] - v;
}
__global__ void k_scan_add() {
    int gid = blockIdx.x * 1024 + threadIdx.x;
    if (gid < NN) {
        int o = d_off[gid] + d_blkoff[blockIdx.x];
        d_off[gid] = o;
        d_pos[gid] = o;
    }
    if (gid == 0) d_off[NN] = NE;
}

__global__ void k_fill(const void* __restrict__ ei) {
    int e = blockIdx.x * 256 + threadIdx.x;
    if (e >= NE) return;
    int r = edge_idx(ei, 0, e);
    int c = edge_idx(ei, 1, e);
    int p = atomicAdd(&d_pos[c], 1);
    d_adj[p] = make_int2(r, __float_as_int(d_dis[r]));
}

// ---------------- CSR gather: one warp per node ----------------
__global__ __launch_bounds__(256) void k_gather(const float* __restrict__ b1,
                                                int phase) {
    int node = (blockIdx.x * 256 + threadIdx.x) >> 5;
    if (node >= NN) return;
    int lane = threadIdx.x & 31;
    const float* __restrict__ src = phase ? d_Cb : d_A;
    float* __restrict__ dst       = phase ? d_B  : d_Cb;
    int beg = d_off[node], end = d_off[node + 1];
    float dc = d_dis[node];

    float4 acc = ((const float4*)(src + (size_t)node * CH))[lane];
    acc.x *= dc; acc.y *= dc; acc.z *= dc; acc.w *= dc;

    for (int base = beg; base < end; base += 32) {
        int t = base + lane;
        int2 pr = (t < end) ? d_adj[t] : make_int2(0, 0);
        int n = min(32, end - base);
#pragma unroll 8
        for (int k = 0; k < n; k++) {
            int   j = __shfl_sync(0xffffffffu, pr.x, k);
            float w = __int_as_float(__shfl_sync(0xffffffffu, pr.y, k));
            float4 v = ((const float4*)(src + (size_t)j * CH))[lane];
            acc.x = fmaf(w, v.x, acc.x);
            acc.y = fmaf(w, v.y, acc.y);
            acc.z = fmaf(w, v.z, acc.z);
            acc.w = fmaf(w, v.w, acc.w);
        }
    }
    acc.x *= dc; acc.y *= dc; acc.z *= dc; acc.w *= dc;

    if (phase == 0) {
        float4 bias = ((const float4*)b1)[lane];
        acc.x = fmaxf(acc.x + bias.x, 0.f);
        acc.y = fmaxf(acc.y + bias.y, 0.f);
        acc.z = fmaxf(acc.z + bias.z, 0.f);
        acc.w = fmaxf(acc.w + bias.w, 0.f);
    }
    ((float4*)(dst + (size_t)node * CH))[lane] = acc;
}

// ---------------- final: [mu|lv] = g @ [Wmu|Wlv] (tensor) + reparam ----------
__global__ __launch_bounds__(256) void k_final_tc(const float* __restrict__ bmu,
                                                  const float* __restrict__ blv,
                                                  const float* __restrict__ eps,
                                                  float* __restrict__ out) {
    float acc[16][4];
#pragma unroll
    for (int j = 0; j < 16; j++) acc[j][0] = acc[j][1] = acc[j][2] = acc[j][3] = 0.f;
    int row0 = blockIdx.x * 128;
    gemm_tc_loop(d_B, d_Fmlhi, d_Fmllo, row0, acc);

    int lane = threadIdx.x & 31, warp = threadIdx.x >> 5;
    int g = lane >> 2, tig = lane & 3;
    int r0 = row0 + warp * 16 + g, r1 = r0 + 8;

    float* out_z  = out;
    float* out_mu = out + (size_t)NN * LAT;
    float* out_lv = out + 2 * (size_t)NN * LAT;

#pragma unroll
    for (int j = 0; j < 8; j++) {               // mu tiles; lv = tile j+8
        int col = j * 8 + 2 * tig;
        float2 bm = *(const float2*)(bmu + col);
        float2 bl = *(const float2*)(blv + col);
        if (r0 < NN) {
            float m0 = acc[j][0] + bm.x,     m1 = acc[j][1] + bm.y;
            float l0 = acc[j + 8][0] + bl.x, l1 = acc[j + 8][1] + bl.y;
            float2 ev = *(const float2*)(eps + (size_t)r0 * LAT + col);
            float z0 = m0 + ev.x * expf(0.5f * l0);
            float z1 = m1 + ev.y * expf(0.5f * l1);
            size_t o = (size_t)r0 * LAT + col;
            *(float2*)(out_mu + o) = make_float2(m0, m1);
            *(float2*)(out_lv + o) = make_float2(l0, l1);
            *(float2*)(out_z  + o) = make_float2(z0, z1);
        }
        if (r1 < NN) {
            float m0 = acc[j][2] + bm.x,     m1 = acc[j][3] + bm.y;
            float l0 = acc[j + 8][2] + bl.x, l1 = acc[j + 8][3] + bl.y;
            float2 ev = *(const float2*)(eps + (size_t)r1 * LAT + col);
            float z0 = m0 + ev.x * expf(0.5f * l0);
            float z1 = m1 + ev.y * expf(0.5f * l1);
            size_t o = (size_t)r1 * LAT + col;
            *(float2*)(out_mu + o) = make_float2(m0, m1);
            *(float2*)(out_lv + o) = make_float2(l0, l1);
            *(float2*)(out_z  + o) = make_float2(z0, z1);
        }
    }
}

// ---------------- launch ----------------
extern "C" void kernel_launch(void* const* d_in, const int* in_sizes, int n_in,
                              void* d_out, int out_size) {
    const float* x   = (const float*)d_in[0];
    const void*  ei  = d_in[1];
    const float* W1  = (const float*)d_in[2];
    const float* b1  = (const float*)d_in[3];
    const float* Wmu = (const float*)d_in[4];
    const float* bmu = (const float*)d_in[5];
    const float* Wlv = (const float*)d_in[6];
    const float* blv = (const float*)d_in[7];
    const float* eps = (const float*)d_in[8];
    float* out = (float*)d_out;

    k_wsplit<<<64, 256>>>(W1, Wmu, Wlv);                      // 1
    k_detect_zero<<<(NN + 255) / 256, 256>>>((const int*)ei); // 2
    k_hist<<<(NE + 255) / 256, 256>>>(ei);                    // 3
    k_gemm1_tc<<<GBLK, 256>>>(x);                             // 4 (profiled slot)
    k_scan_local<<<NBLK_SCAN, 1024>>>();                      // 5
    k_scan_blk<<<1, 128>>>();                                 // 6
    k_scan_add<<<NBLK_SCAN, 1024>>>();                        // 7
    k_fill<<<(NE + 255) / 256, 256>>>(ei);                    // 8

    k_gather<<<(NN * 32 + 255) / 256, 256>>>(b1, 0);          // 9
    k_gather<<<(NN * 32 + 255) / 256, 256>>>(b1, 1);          // 10

    k_final_tc<<<GBLK, 256>>>(bmu, blv, eps, out);            // 11
}